// round 1
// baseline (speedup 1.0000x reference)
#include <cuda_runtime.h>
#include <cstdint>

// Problem constants (shapes are fixed by the dataset).
#define BATCH 16
#define DDIM  1024
#define KDIM  64
#define FDIM  128     // 2*K
#define NMAX  8192

// GEMM tiling
#define BM 128
#define BN 128
#define TM 8
#define TN 8
#define NTHREADS 256
#define AS_STRIDE (BM + 4)   // 132 floats, 16B-aligned row stride, pad kills bank conflicts
#define BS_STRIDE (BN + 4)   // 132
#define SMEM_FLOATS (FDIM * AS_STRIDE + FDIM * BS_STRIDE)
#define SMEM_BYTES  (SMEM_FLOATS * 4)

// fp32 constants mirroring the reference's fp32 math
#define TWO_PI_F 6.28318548202514648438f   // fl(2*pi)
#define PI2_HI   6.28318548202514648438f   // hi part of real 2*pi
#define PI2_LO  -1.74845553e-7f            // 2*pi - PI2_HI
#define INV_2PI  0.15915494309189535f

__global__ void __launch_bounds__(NTHREADS, 1)
cyc_pos_gemm_kernel(const int* __restrict__ lengths,
                    const float* __restrict__ W,
                    float* __restrict__ out)
{
    extern __shared__ float smem[];
    float* As = smem;                      // [FDIM][AS_STRIDE]  feats^T tile
    float* Bs = smem + FDIM * AS_STRIDE;   // [FDIM][BS_STRIDE]  W^T tile

    const int tid = threadIdx.x;
    const int by  = blockIdx.y;
    const int b   = by >> 6;               // NMAX/BM = 64 row-tiles per batch
    const int n0  = (by & 63) * BM;
    const int d0  = blockIdx.x * BN;

    const int   L  = lengths[b];
    const float Lf = (float)L;

    // ---- Generate feats tile: As[f][row] = amp * {cos,sin}(n * Delta_k), masked ----
    // Reference math in fp32: Delta = fl(fl(2pi)*k)/L ; theta = fl(n * Delta).
    // We range-reduce theta by exact multiples of the REAL 2*pi (double-float HI+LO)
    // so sincos sees |r| <= pi even under fast-math.
    #pragma unroll
    for (int it = 0; it < (BM * KDIM) / NTHREADS; ++it) {   // 32 iters
        int idx = it * NTHREADS + tid;
        int k   = (idx & (KDIM - 1)) + 1;   // 1..64
        int row = idx >> 6;
        int n   = n0 + row;

        float Delta = (TWO_PI_F * (float)k) / Lf;
        float theta = (float)n * Delta;

        float q = rintf(theta * INV_2PI);
        float r = fmaf(-q, PI2_HI, theta);
        r       = fmaf(-q, PI2_LO, r);

        float s, c;
        sincosf(r, &s, &c);

        float m = (n < L) ? 0.125f : 0.0f;  // amp = 1/sqrt(K), mask fused in
        int f = 2 * (k - 1);
        As[(f    ) * AS_STRIDE + row] = c * m;
        As[(f + 1) * AS_STRIDE + row] = s * m;
    }

    // ---- Load + transpose W tile: Bs[f][di] = W[d0+di][f] ----
    {
        const float4* W4 = reinterpret_cast<const float4*>(W + (size_t)d0 * FDIM);
        const int f4 = tid & 31;       // float4 index along f
        const int dw = tid >> 5;       // 0..7
        #pragma unroll
        for (int it = 0; it < 16; ++it) {
            int di = it * 8 + dw;
            float4 v = W4[di * 32 + f4];
            int f = f4 * 4;
            Bs[(f + 0) * BS_STRIDE + di] = v.x;
            Bs[(f + 1) * BS_STRIDE + di] = v.y;
            Bs[(f + 2) * BS_STRIDE + di] = v.z;
            Bs[(f + 3) * BS_STRIDE + di] = v.w;
        }
    }
    __syncthreads();

    // ---- Register-tiled GEMM: acc[i][j] += As[f][trow+i] * Bs[f][tcol+j] ----
    const int trow = (tid >> 4) * TM;   // 0..120
    const int tcol = (tid & 15) * TN;   // 0..120

    float acc[TM][TN];
    #pragma unroll
    for (int i = 0; i < TM; ++i)
        #pragma unroll
        for (int j = 0; j < TN; ++j)
            acc[i][j] = 0.0f;

    #pragma unroll 8
    for (int f = 0; f < FDIM; ++f) {
        float a[TM], bb[TN];
        const float4* ap = reinterpret_cast<const float4*>(&As[f * AS_STRIDE + trow]);
        const float4* bp = reinterpret_cast<const float4*>(&Bs[f * BS_STRIDE + tcol]);
        float4 a0 = ap[0], a1 = ap[1];
        float4 b0 = bp[0], b1 = bp[1];
        a[0]=a0.x; a[1]=a0.y; a[2]=a0.z; a[3]=a0.w;
        a[4]=a1.x; a[5]=a1.y; a[6]=a1.z; a[7]=a1.w;
        bb[0]=b0.x; bb[1]=b0.y; bb[2]=b0.z; bb[3]=b0.w;
        bb[4]=b1.x; bb[5]=b1.y; bb[6]=b1.z; bb[7]=b1.w;
        #pragma unroll
        for (int i = 0; i < TM; ++i)
            #pragma unroll
            for (int j = 0; j < TN; ++j)
                acc[i][j] = fmaf(a[i], bb[j], acc[i][j]);
    }

    // ---- Store 8x8 tile (rows masked beyond length are naturally zero) ----
    size_t outBase = ((size_t)(b * NMAX + n0 + trow)) * DDIM + d0 + tcol;
    #pragma unroll
    for (int i = 0; i < TM; ++i) {
        float4* o = reinterpret_cast<float4*>(out + outBase + (size_t)i * DDIM);
        o[0] = make_float4(acc[i][0], acc[i][1], acc[i][2], acc[i][3]);
        o[1] = make_float4(acc[i][4], acc[i][5], acc[i][6], acc[i][7]);
    }
}

// Optional second output: mask [B, NMAX] as 0/1 in the output dtype.
__global__ void mask_kernel(const int* __restrict__ lengths, float* __restrict__ mask_out)
{
    int idx = blockIdx.x * blockDim.x + threadIdx.x;   // < BATCH*NMAX
    int b = idx >> 13;            // NMAX = 8192 = 2^13
    int n = idx & (NMAX - 1);
    mask_out[idx] = (n < lengths[b]) ? 1.0f : 0.0f;
}

extern "C" void kernel_launch(void* const* d_in, const int* in_sizes, int n_in,
                              void* d_out, int out_size)
{
    const int*   lengths = (const int*)d_in[0];
    const float* W       = (const float*)d_in[1];
    float*       out     = (float*)d_out;
    (void)in_sizes; (void)n_in;

    cudaFuncSetAttribute(cyc_pos_gemm_kernel,
                         cudaFuncAttributeMaxDynamicSharedMemorySize, SMEM_BYTES);

    dim3 grid(DDIM / BN, (BATCH * NMAX) / BM);   // (8, 1024)
    cyc_pos_gemm_kernel<<<grid, NTHREADS, SMEM_BYTES>>>(lengths, W, out);

    long long pos_elems = (long long)BATCH * NMAX * DDIM;   // 134217728
    if ((long long)out_size >= pos_elems + (long long)BATCH * NMAX) {
        mask_kernel<<<(BATCH * NMAX) / 256, 256>>>(lengths, out + pos_elems);
    }
}

// round 3
// speedup vs baseline: 3.6820x; 3.6820x over previous
#include <cuda_runtime.h>
#include <cuda_bf16.h>
#include <cstdint>

// ---------------------------------------------------------------------------
// Problem constants
// ---------------------------------------------------------------------------
#define BATCH 16
#define DDIM  1024
#define NMAX  8192
#define MTOT  (BATCH * NMAX)     // 131072 rows
#define MT    1024               // M tiles of 128 rows
#define NT    8                  // N tiles of 128 cols

// fp32 constants mirroring the reference's fp32 math
#define TWO_PI_F 6.28318548202514648438f
#define PI2_HI   6.28318548202514648438f
#define PI2_LO  -1.74845553e-7f
#define INV_2PI  0.15915494309189535f

// W images: per ntile 64KB = hi tile (32KB: 128 rows x 128 bf16, swizzled 256B rows)
// followed by lo tile (32KB). Total 512KB, L2-resident.
__device__ __align__(1024) static unsigned char g_B[(size_t)NT * 65536];

// ---------------------------------------------------------------------------
// Helpers
// ---------------------------------------------------------------------------
__device__ __forceinline__ uint32_t smem_u32(const void* p) {
    uint32_t a;
    asm("{ .reg .u64 t; cvta.to.shared.u64 t, %1; cvt.u32.u64 %0, t; }" : "=r"(a) : "l"(p));
    return a;
}

// Swizzled byte offset inside a 128x128 bf16 tile (256B rows):
// XOR the 16B-chunk index with (row & 7) -> conflict-free ldmatrix.
__device__ __forceinline__ unsigned sw(unsigned row, unsigned kb) {
    return row * 256u + (kb ^ ((row & 7u) << 4));
}

__device__ __forceinline__ unsigned pack2(__nv_bfloat16 a, __nv_bfloat16 b) {
    return (unsigned)__bfloat16_as_ushort(a) | ((unsigned)__bfloat16_as_ushort(b) << 16);
}

#define CP_ASYNC16(sm, gp) \
    asm volatile("cp.async.cg.shared.global [%0], [%1], 16;" :: "r"(sm), "l"(gp))
#define CP_ASYNC_COMMIT() asm volatile("cp.async.commit_group;" ::: "memory")
#define CP_ASYNC_WAIT0()  asm volatile("cp.async.wait_group 0;" ::: "memory")

#define LDSM_X4(r, addr) \
    asm volatile("ldmatrix.sync.aligned.m8n8.x4.shared.b16 {%0,%1,%2,%3}, [%4];" \
        : "=r"((r)[0]), "=r"((r)[1]), "=r"((r)[2]), "=r"((r)[3]) : "r"(addr))

#define MMA16816(c, a, b0v, b1v) \
    asm volatile("mma.sync.aligned.m16n8k16.row.col.f32.bf16.bf16.f32 " \
        "{%0,%1,%2,%3}, {%4,%5,%6,%7}, {%8,%9}, {%0,%1,%2,%3};" \
        : "+f"((c)[0]), "+f"((c)[1]), "+f"((c)[2]), "+f"((c)[3]) \
        : "r"((a)[0]), "r"((a)[1]), "r"((a)[2]), "r"((a)[3]), "r"(b0v), "r"(b1v))

// ---------------------------------------------------------------------------
// W prep: W[1024,128] fp32 -> bf16 hi/lo split, swizzled per-ntile tile images
// One work item = 8 consecutive features (16B) of one d-row.
// ---------------------------------------------------------------------------
__global__ void __launch_bounds__(256) wprep_kernel(const float* __restrict__ W)
{
    int idx  = blockIdx.x * 256 + threadIdx.x;     // < 8*128*16 = 16384
    int nt   = idx >> 11;
    int rem  = idx & 2047;
    int drow = rem >> 4;
    int kg   = rem & 15;

    const float* wr = W + (size_t)(nt * 128 + drow) * 128 + kg * 8;
    unsigned hi[4], lo[4];
    #pragma unroll
    for (int j = 0; j < 4; ++j) {
        float a = wr[2 * j], bb = wr[2 * j + 1];
        __nv_bfloat16 ah = __float2bfloat16(a);
        __nv_bfloat16 bh = __float2bfloat16(bb);
        __nv_bfloat16 al = __float2bfloat16(a - __bfloat162float(ah));
        __nv_bfloat16 bl = __float2bfloat16(bb - __bfloat162float(bh));
        hi[j] = pack2(ah, bh);
        lo[j] = pack2(al, bl);
    }
    unsigned char* base = g_B + (size_t)nt * 65536;
    unsigned off = sw((unsigned)drow, (unsigned)kg * 16);
    *reinterpret_cast<uint4*>(base + off)         = make_uint4(hi[0], hi[1], hi[2], hi[3]);
    *reinterpret_cast<uint4*>(base + 32768 + off) = make_uint4(lo[0], lo[1], lo[2], lo[3]);
}

// ---------------------------------------------------------------------------
// Fused gen + GEMM kernel.
// smem: A_hi [0,32K), A_lo [32K,64K), B buf0 [64K,128K), B buf1 [128K,192K)
// ---------------------------------------------------------------------------
#define SMEM_A    0
#define SMEM_B    65536
#define SMEM_TOTAL 196608

__global__ void __launch_bounds__(256, 1)
gemm_kernel(const int* __restrict__ lengths, float* __restrict__ out)
{
    extern __shared__ unsigned char smem[];
    const uint32_t sb = smem_u32(smem);
    const int tid  = threadIdx.x;
    const int lane = tid & 31;
    const int wid  = tid >> 5;

    const int mtile = blockIdx.x;          // 0..1023
    const int b     = mtile >> 6;
    const int n0    = (mtile & 63) * 128;

    const int   L  = lengths[b];
    const float Lf = (float)L;

    // ---- Generate feats tile (bf16 hi/lo split, masked, swizzled) ----
    #pragma unroll
    for (int it = 0; it < 8; ++it) {
        int idx = it * 256 + tid;          // 2048 items: 128 rows x 16 kgroups
        int row = idx >> 4;
        int kg  = idx & 15;
        int n   = n0 + row;
        float nf = (float)n;
        float m  = (n < L) ? 0.125f : 0.0f;  // amp 1/sqrt(K) fused with mask

        unsigned hi[4], lo[4];
        #pragma unroll
        for (int j = 0; j < 4; ++j) {
            int k = kg * 4 + j + 1;
            float Delta = (TWO_PI_F * (float)k) / Lf;
            float theta = nf * Delta;
            float q = rintf(theta * INV_2PI);
            float r = fmaf(-q, PI2_HI, theta);
            r       = fmaf(-q, PI2_LO, r);
            float s, c;
            sincosf(r, &s, &c);
            float vc = c * m, vs = s * m;
            __nv_bfloat16 ch = __float2bfloat16(vc);
            __nv_bfloat16 sh = __float2bfloat16(vs);
            __nv_bfloat16 cl = __float2bfloat16(vc - __bfloat162float(ch));
            __nv_bfloat16 sl = __float2bfloat16(vs - __bfloat162float(sh));
            hi[j] = pack2(ch, sh);
            lo[j] = pack2(cl, sl);
        }
        unsigned off = sw((unsigned)row, (unsigned)kg * 16);
        *reinterpret_cast<uint4*>(smem + SMEM_A + off)         = make_uint4(hi[0], hi[1], hi[2], hi[3]);
        *reinterpret_cast<uint4*>(smem + SMEM_A + 32768 + off) = make_uint4(lo[0], lo[1], lo[2], lo[3]);
    }

    // ---- Prologue: async-copy B tile 0 into buf0 ----
    #pragma unroll
    for (int it = 0; it < 16; ++it)
        CP_ASYNC16(sb + SMEM_B + it * 4096 + tid * 16, g_B + it * 4096 + tid * 16);
    CP_ASYNC_COMMIT();

    // ---- Per-thread ldmatrix address components ----
    // A fragment (m16k16, x4): row = m0 + (lane & 15), k-halve = (lane & 16) bytes
    const unsigned m0    = (unsigned)wid * 16u;
    const unsigned aRow  = m0 + (unsigned)(lane & 15);
    const unsigned aXr   = (aRow & 7u) << 4;
    const unsigned aC0   = (unsigned)(lane & 16);          // 0 or 16 bytes
    const uint32_t aBase = sb + SMEM_A + aRow * 256u;
    // B fragment (k16n8 pair via x4): local row = (lane&7) + ((lane&16)?8:0),
    // k-halve = (lane&8)?16B:0
    const unsigned bRl = (unsigned)((lane & 7) + ((lane & 16) ? 8 : 0));
    const unsigned bXr = (bRl & 7u) << 4;
    const unsigned bC0 = (unsigned)((lane & 8) ? 16 : 0);

    __syncthreads();   // A tile ready

    for (int nt = 0; nt < NT; ++nt) {
        CP_ASYNC_WAIT0();
        __syncthreads();   // B tile nt ready; all warps done with the other buffer

        if (nt + 1 < NT) {
            const unsigned char* gBn = g_B + (size_t)(nt + 1) * 65536;
            uint32_t bo = sb + SMEM_B + (unsigned)((nt + 1) & 1) * 65536u;
            #pragma unroll
            for (int it = 0; it < 16; ++it)
                CP_ASYNC16(bo + it * 4096 + tid * 16, gBn + it * 4096 + tid * 16);
            CP_ASYNC_COMMIT();
        }

        const uint32_t bBase = sb + SMEM_B + (unsigned)(nt & 1) * 65536u;

        float acc[16][4];
        #pragma unroll
        for (int i = 0; i < 16; ++i)
            #pragma unroll
            for (int j = 0; j < 4; ++j) acc[i][j] = 0.0f;

        #pragma unroll
        for (int ks = 0; ks < 8; ++ks) {
            const unsigned akb = (unsigned)ks * 32u + aC0;
            uint32_t ah[4], al[4];
            LDSM_X4(ah, aBase + (akb ^ aXr));
            LDSM_X4(al, aBase + 32768u + (akb ^ aXr));

            const unsigned bkb = ((unsigned)ks * 32u + bC0) ^ bXr;
            #pragma unroll
            for (int np = 0; np < 8; ++np) {
                uint32_t baddr = bBase + (np * 16u + bRl) * 256u + bkb;
                uint32_t bh[4], bl[4];
                LDSM_X4(bh, baddr);
                LDSM_X4(bl, baddr + 32768u);
                // 3-pass split: hi*hi + lo*hi + hi*lo (lo*lo dropped, ~2^-34)
                MMA16816(acc[2 * np],     ah, bh[0], bh[1]);
                MMA16816(acc[2 * np],     al, bh[0], bh[1]);
                MMA16816(acc[2 * np],     ah, bl[0], bl[1]);
                MMA16816(acc[2 * np + 1], ah, bh[2], bh[3]);
                MMA16816(acc[2 * np + 1], al, bh[2], bh[3]);
                MMA16816(acc[2 * np + 1], ah, bl[2], bl[3]);
            }
        }

        // ---- Epilogue: registers -> gmem (full 32B sectors) ----
        const int r0 = lane >> 2;
        const int c0 = (lane & 3) * 2;
        size_t ob = ((size_t)(mtile * 128) + m0) * DDIM + (size_t)nt * 128;
        #pragma unroll
        for (int t8 = 0; t8 < 16; ++t8) {
            float2 v0 = make_float2(acc[t8][0], acc[t8][1]);
            float2 v1 = make_float2(acc[t8][2], acc[t8][3]);
            *reinterpret_cast<float2*>(&out[ob + (size_t)r0 * DDIM + t8 * 8 + c0])       = v0;
            *reinterpret_cast<float2*>(&out[ob + (size_t)(r0 + 8) * DDIM + t8 * 8 + c0]) = v1;
        }
    }
}

// ---------------------------------------------------------------------------
// Mask tail output (only if the harness output includes it)
// ---------------------------------------------------------------------------
__global__ void mask_kernel(const int* __restrict__ lengths, float* __restrict__ mask_out)
{
    int idx = blockIdx.x * blockDim.x + threadIdx.x;
    int b = idx >> 13;
    int n = idx & (NMAX - 1);
    mask_out[idx] = (n < lengths[b]) ? 1.0f : 0.0f;
}

// ---------------------------------------------------------------------------
extern "C" void kernel_launch(void* const* d_in, const int* in_sizes, int n_in,
                              void* d_out, int out_size)
{
    const int*   lengths = (const int*)d_in[0];
    const float* W       = (const float*)d_in[1];
    float*       out     = (float*)d_out;
    (void)in_sizes; (void)n_in;

    cudaFuncSetAttribute(gemm_kernel,
                         cudaFuncAttributeMaxDynamicSharedMemorySize, SMEM_TOTAL);

    wprep_kernel<<<64, 256>>>(W);
    gemm_kernel<<<MT, 256, SMEM_TOTAL>>>(lengths, out);

    long long pos_elems = (long long)MTOT * DDIM;
    if ((long long)out_size >= pos_elems + (long long)MTOT) {
        mask_kernel<<<MTOT / 256, 256>>>(lengths, out + pos_elems);
    }
}

// round 4
// speedup vs baseline: 5.3535x; 1.4539x over previous
#include <cuda_runtime.h>
#include <cuda_fp16.h>
#include <cstdint>

// ---------------------------------------------------------------------------
// Problem constants
// ---------------------------------------------------------------------------
#define BATCH 16
#define DDIM  1024
#define NMAX  8192
#define MTOT  (BATCH * NMAX)     // 131072 rows
#define MT    1024               // M tiles of 128 rows
#define NT    8                  // N tiles of 128 cols

// fp32 constants mirroring the reference's fp32 math
#define TWO_PI_F 6.28318548202514648438f
#define PI2_HI   6.28318548202514648438f
#define PI2_LO  -1.74845553e-7f
#define INV_2PI  0.15915494309189535f

// W images: per ntile 32KB (128 d-rows x 128 fp16, swizzled 256B rows). 256KB, L2-resident.
__device__ __align__(1024) static unsigned char g_B[(size_t)NT * 32768];

// ---------------------------------------------------------------------------
// Helpers
// ---------------------------------------------------------------------------
__device__ __forceinline__ uint32_t smem_u32(const void* p) {
    uint32_t a;
    asm("{ .reg .u64 t; cvta.to.shared.u64 t, %1; cvt.u32.u64 %0, t; }" : "=r"(a) : "l"(p));
    return a;
}

// Swizzled byte offset inside a 128x128 fp16 tile (256B rows):
// XOR the 16B-chunk index with (row & 7) -> conflict-free ldmatrix.
__device__ __forceinline__ unsigned sw(unsigned row, unsigned kb) {
    return row * 256u + (kb ^ ((row & 7u) << 4));
}

__device__ __forceinline__ unsigned packh2(__half a, __half b) {
    return (unsigned)__half_as_ushort(a) | ((unsigned)__half_as_ushort(b) << 16);
}

#define CP_ASYNC16(sm, gp) \
    asm volatile("cp.async.cg.shared.global [%0], [%1], 16;" :: "r"(sm), "l"(gp))
#define CP_ASYNC_COMMIT() asm volatile("cp.async.commit_group;" ::: "memory")
#define CP_ASYNC_WAIT0()  asm volatile("cp.async.wait_group 0;" ::: "memory")

#define LDSM_X4(r, addr) \
    asm volatile("ldmatrix.sync.aligned.m8n8.x4.shared.b16 {%0,%1,%2,%3}, [%4];" \
        : "=r"((r)[0]), "=r"((r)[1]), "=r"((r)[2]), "=r"((r)[3]) : "r"(addr))

#define MMA16816(c, a, b0v, b1v) \
    asm volatile("mma.sync.aligned.m16n8k16.row.col.f32.f16.f16.f32 " \
        "{%0,%1,%2,%3}, {%4,%5,%6,%7}, {%8,%9}, {%0,%1,%2,%3};" \
        : "+f"((c)[0]), "+f"((c)[1]), "+f"((c)[2]), "+f"((c)[3]) \
        : "r"((a)[0]), "r"((a)[1]), "r"((a)[2]), "r"((a)[3]), "r"(b0v), "r"(b1v))

// ---------------------------------------------------------------------------
// W prep: W[1024,128] fp32 -> fp16, swizzled per-ntile tile images
// ---------------------------------------------------------------------------
__global__ void __launch_bounds__(256) wprep_kernel(const float* __restrict__ W)
{
    int idx  = blockIdx.x * 256 + threadIdx.x;     // < 8*128*16 = 16384
    int nt   = idx >> 11;
    int rem  = idx & 2047;
    int drow = rem >> 4;
    int kg   = rem & 15;

    const float* wr = W + (size_t)(nt * 128 + drow) * 128 + kg * 8;
    unsigned hi[4];
    #pragma unroll
    for (int j = 0; j < 4; ++j)
        hi[j] = packh2(__float2half_rn(wr[2 * j]), __float2half_rn(wr[2 * j + 1]));
    unsigned char* base = g_B + (size_t)nt * 32768;
    *reinterpret_cast<uint4*>(base + sw((unsigned)drow, (unsigned)kg * 16)) =
        make_uint4(hi[0], hi[1], hi[2], hi[3]);
}

// ---------------------------------------------------------------------------
// Fused gen + GEMM kernel.
// smem: A_hi [0,32K), A_lo [32K,64K), B buf0 [64K,96K), B buf1 [96K,128K)
// ---------------------------------------------------------------------------
#define SMEM_A     0
#define SMEM_B     65536
#define SMEM_TOTAL 131072

__global__ void __launch_bounds__(256, 1)
gemm_kernel(const int* __restrict__ lengths, float* __restrict__ out)
{
    extern __shared__ unsigned char smem[];
    const uint32_t sb = smem_u32(smem);
    const int tid  = threadIdx.x;
    const int lane = tid & 31;
    const int wid  = tid >> 5;

    const int mtile = blockIdx.x;          // 0..1023
    const int b     = mtile >> 6;
    const int n0    = (mtile & 63) * 128;

    const int   L  = lengths[b];
    const float Lf = (float)L;

    // ---- Fast path: fully-masked tile -> pure zero fill, no compute ----
    if (n0 >= L) {
        uint4 z = make_uint4(0u, 0u, 0u, 0u);
        uint4* dst = reinterpret_cast<uint4*>(out + (size_t)mtile * 128 * DDIM);
        #pragma unroll 4
        for (int i = tid; i < (128 * DDIM) / 4; i += 256) dst[i] = z;
        return;
    }

    // ---- Prologue: async-copy B tile 0 into buf0 (starts before gen) ----
    #pragma unroll
    for (int it = 0; it < 8; ++it)
        CP_ASYNC16(sb + SMEM_B + it * 4096 + tid * 16, g_B + it * 4096 + tid * 16);
    CP_ASYNC_COMMIT();

    // ---- Generate feats tile (fp16 hi/lo split of A, masked, swizzled) ----
    #pragma unroll
    for (int it = 0; it < 8; ++it) {
        int idx = it * 256 + tid;          // 2048 items: 128 rows x 16 kgroups
        int row = idx >> 4;
        int kg  = idx & 15;
        int n   = n0 + row;
        float nf = (float)n;
        float m  = (n < L) ? 0.125f : 0.0f;  // amp 1/sqrt(K) fused with mask

        unsigned hi[4], lo[4];
        #pragma unroll
        for (int j = 0; j < 4; ++j) {
            int k = kg * 4 + j + 1;
            float Delta = (TWO_PI_F * (float)k) / Lf;
            float theta = nf * Delta;
            float q = rintf(theta * INV_2PI);
            float r = fmaf(-q, PI2_HI, theta);
            r       = fmaf(-q, PI2_LO, r);
            float s, c;
            __sincosf(r, &s, &c);
            float vc = c * m, vs = s * m;
            __half ch = __float2half_rn(vc);
            __half sh = __float2half_rn(vs);
            __half cl = __float2half_rn(vc - __half2float(ch));
            __half sl = __float2half_rn(vs - __half2float(sh));
            hi[j] = packh2(ch, sh);
            lo[j] = packh2(cl, sl);
        }
        unsigned off = sw((unsigned)row, (unsigned)kg * 16);
        *reinterpret_cast<uint4*>(smem + SMEM_A + off)         = make_uint4(hi[0], hi[1], hi[2], hi[3]);
        *reinterpret_cast<uint4*>(smem + SMEM_A + 32768 + off) = make_uint4(lo[0], lo[1], lo[2], lo[3]);
    }

    // ---- Per-thread ldmatrix address components ----
    const unsigned m0    = (unsigned)wid * 16u;
    const unsigned aRow  = m0 + (unsigned)(lane & 15);
    const unsigned aXr   = (aRow & 7u) << 4;
    const unsigned aC0   = (unsigned)(lane & 16);          // 0 or 16 bytes
    const uint32_t aBase = sb + SMEM_A + aRow * 256u;
    const unsigned bRl = (unsigned)((lane & 7) + ((lane & 16) ? 8 : 0));
    const unsigned bXr = (bRl & 7u) << 4;
    const unsigned bC0 = (unsigned)((lane & 8) ? 16 : 0);

    __syncthreads();   // A tile ready

    for (int nt = 0; nt < NT; ++nt) {
        CP_ASYNC_WAIT0();
        __syncthreads();   // B tile nt ready; all warps done with the other buffer

        if (nt + 1 < NT) {
            const unsigned char* gBn = g_B + (size_t)(nt + 1) * 32768;
            uint32_t bo = sb + SMEM_B + (unsigned)((nt + 1) & 1) * 32768u;
            #pragma unroll
            for (int it = 0; it < 8; ++it)
                CP_ASYNC16(bo + it * 4096 + tid * 16, gBn + it * 4096 + tid * 16);
            CP_ASYNC_COMMIT();
        }

        const uint32_t bBase = sb + SMEM_B + (unsigned)(nt & 1) * 32768u;

        float acc[16][4];
        #pragma unroll
        for (int i = 0; i < 16; ++i)
            #pragma unroll
            for (int j = 0; j < 4; ++j) acc[i][j] = 0.0f;

        #pragma unroll
        for (int ks = 0; ks < 8; ++ks) {
            const unsigned akb = ((unsigned)ks * 32u + aC0) ^ aXr;
            uint32_t ah[4], al[4];
            LDSM_X4(ah, aBase + akb);
            LDSM_X4(al, aBase + 32768u + akb);

            const unsigned bkb = ((unsigned)ks * 32u + bC0) ^ bXr;
            #pragma unroll
            for (int np = 0; np < 8; ++np) {
                uint32_t bh[4];
                LDSM_X4(bh, bBase + (np * 16u + bRl) * 256u + bkb);
                // 2-pass fp16 split: (hiA + loA) * fl16(B); dropped A*loB ~ 2^-12 rel
                MMA16816(acc[2 * np],     ah, bh[0], bh[1]);
                MMA16816(acc[2 * np],     al, bh[0], bh[1]);
                MMA16816(acc[2 * np + 1], ah, bh[2], bh[3]);
                MMA16816(acc[2 * np + 1], al, bh[2], bh[3]);
            }
        }

        // ---- Epilogue: registers -> gmem (full 32B sectors) ----
        const int r0 = lane >> 2;
        const int c0 = (lane & 3) * 2;
        size_t ob = ((size_t)(mtile * 128) + m0) * DDIM + (size_t)nt * 128;
        #pragma unroll
        for (int t8 = 0; t8 < 16; ++t8) {
            float2 v0 = make_float2(acc[t8][0], acc[t8][1]);
            float2 v1 = make_float2(acc[t8][2], acc[t8][3]);
            *reinterpret_cast<float2*>(&out[ob + (size_t)r0 * DDIM + t8 * 8 + c0])       = v0;
            *reinterpret_cast<float2*>(&out[ob + (size_t)(r0 + 8) * DDIM + t8 * 8 + c0]) = v1;
        }
    }
}

// ---------------------------------------------------------------------------
// Mask tail output (only if the harness output includes it)
// ---------------------------------------------------------------------------
__global__ void mask_kernel(const int* __restrict__ lengths, float* __restrict__ mask_out)
{
    int idx = blockIdx.x * blockDim.x + threadIdx.x;
    int b = idx >> 13;
    int n = idx & (NMAX - 1);
    mask_out[idx] = (n < lengths[b]) ? 1.0f : 0.0f;
}

// ---------------------------------------------------------------------------
extern "C" void kernel_launch(void* const* d_in, const int* in_sizes, int n_in,
                              void* d_out, int out_size)
{
    const int*   lengths = (const int*)d_in[0];
    const float* W       = (const float*)d_in[1];
    float*       out     = (float*)d_out;
    (void)in_sizes; (void)n_in;

    cudaFuncSetAttribute(gemm_kernel,
                         cudaFuncAttributeMaxDynamicSharedMemorySize, SMEM_TOTAL);

    wprep_kernel<<<64, 256>>>(W);
    gemm_kernel<<<MT, 256, SMEM_TOTAL>>>(lengths, out);

    long long pos_elems = (long long)MTOT * DDIM;
    if ((long long)out_size >= pos_elems + (long long)MTOT) {
        mask_kernel<<<MTOT / 256, 256>>>(lengths, out + pos_elems);
    }
}

// round 6
// speedup vs baseline: 7.4367x; 1.3891x over previous
#include <cuda_runtime.h>
#include <cuda_fp16.h>
#include <cstdint>

// ---------------------------------------------------------------------------
// Problem constants
// ---------------------------------------------------------------------------
#define BATCH 16
#define DDIM  1024
#define NMAX  8192
#define MTOT  (BATCH * NMAX)     // 131072 rows
#define MT    1024               // M tiles of 128 rows
#define NT    8                  // N tiles of 128 cols

// fp32 constants mirroring the reference's fp32 math
#define TWO_PI_F 6.28318548202514648438f
#define PI2_HI   6.28318548202514648438f
#define PI2_LO  -1.74845553e-7f
#define INV_2PI  0.15915494309189535f

// W images: per ntile 32KB (128 d-rows x 128 fp16, swizzled 256B rows). 256KB, L2-resident.
__device__ __align__(1024) static unsigned char g_B[(size_t)NT * 32768];

// ---------------------------------------------------------------------------
// Helpers
// ---------------------------------------------------------------------------
__device__ __forceinline__ uint32_t smem_u32(const void* p) {
    uint32_t a;
    asm("{ .reg .u64 t; cvta.to.shared.u64 t, %1; cvt.u32.u64 %0, t; }" : "=r"(a) : "l"(p));
    return a;
}

// Swizzled byte offset inside a 128x128 fp16 tile (256B rows):
// XOR the 16B-chunk index with (row & 7) -> conflict-free ldmatrix.
__device__ __forceinline__ unsigned sw(unsigned row, unsigned kb) {
    return row * 256u + (kb ^ ((row & 7u) << 4));
}

__device__ __forceinline__ unsigned packh2(__half a, __half b) {
    return (unsigned)__half_as_ushort(a) | ((unsigned)__half_as_ushort(b) << 16);
}

#define CP_ASYNC16(sm, gp) \
    asm volatile("cp.async.cg.shared.global [%0], [%1], 16;" :: "r"(sm), "l"(gp))
#define CP_ASYNC_COMMIT() asm volatile("cp.async.commit_group;" ::: "memory")
#define CP_ASYNC_WAIT0()  asm volatile("cp.async.wait_group 0;" ::: "memory")

#define LDSM_X4(r, addr) \
    asm volatile("ldmatrix.sync.aligned.m8n8.x4.shared.b16 {%0,%1,%2,%3}, [%4];" \
        : "=r"((r)[0]), "=r"((r)[1]), "=r"((r)[2]), "=r"((r)[3]) : "r"(addr))

#define MMA16816(c, a, b0v, b1v) \
    asm volatile("mma.sync.aligned.m16n8k16.row.col.f32.f16.f16.f32 " \
        "{%0,%1,%2,%3}, {%4,%5,%6,%7}, {%8,%9}, {%0,%1,%2,%3};" \
        : "+f"((c)[0]), "+f"((c)[1]), "+f"((c)[2]), "+f"((c)[3]) \
        : "r"((a)[0]), "r"((a)[1]), "r"((a)[2]), "r"((a)[3]), "r"(b0v), "r"(b1v))

// ---------------------------------------------------------------------------
// W prep: W[1024,128] fp32 -> fp16, swizzled per-ntile tile images
// ---------------------------------------------------------------------------
__global__ void __launch_bounds__(256) wprep_kernel(const float* __restrict__ W)
{
    int idx  = blockIdx.x * 256 + threadIdx.x;     // < 8*128*16 = 16384
    int nt   = idx >> 11;
    int rem  = idx & 2047;
    int drow = rem >> 4;
    int kg   = rem & 15;

    const float* wr = W + (size_t)(nt * 128 + drow) * 128 + kg * 8;
    unsigned hi[4];
    #pragma unroll
    for (int j = 0; j < 4; ++j)
        hi[j] = packh2(__float2half_rn(wr[2 * j]), __float2half_rn(wr[2 * j + 1]));
    unsigned char* base = g_B + (size_t)nt * 32768;
    *reinterpret_cast<uint4*>(base + sw((unsigned)drow, (unsigned)kg * 16)) =
        make_uint4(hi[0], hi[1], hi[2], hi[3]);
}

// ---------------------------------------------------------------------------
// Fused gen + GEMM kernel. Single-pass fp16. 2 CTAs/SM.
// smem: A [0,32K), B buf0 [32K,64K), B buf1 [64K,96K)
// ---------------------------------------------------------------------------
#define SMEM_A     0
#define SMEM_B     32768
#define SMEM_TOTAL 98304

__global__ void __launch_bounds__(256, 2)
gemm_kernel(const int* __restrict__ lengths, float* __restrict__ out)
{
    extern __shared__ unsigned char smem[];
    const uint32_t sb = smem_u32(smem);
    const int tid  = threadIdx.x;
    const int lane = tid & 31;
    const int wid  = tid >> 5;

    const int mtile = blockIdx.x;          // 0..1023
    const int b     = mtile >> 6;
    const int n0    = (mtile & 63) * 128;

    const int   L  = lengths[b];
    const float Lf = (float)L;

    // ---- Fast path: fully-masked tile -> pure zero fill, no compute ----
    if (n0 >= L) {
        uint4 z = make_uint4(0u, 0u, 0u, 0u);
        uint4* dst = reinterpret_cast<uint4*>(out + (size_t)mtile * 128 * DDIM);
        #pragma unroll 4
        for (int i = tid; i < (128 * DDIM) / 4; i += 256) dst[i] = z;
        return;
    }

    // ---- Prologue: async-copy B tile 0 into buf0 (starts before gen) ----
    #pragma unroll
    for (int it = 0; it < 8; ++it)
        CP_ASYNC16(sb + SMEM_B + it * 4096 + tid * 16, g_B + it * 4096 + tid * 16);
    CP_ASYNC_COMMIT();

    // ---- Generate feats tile (fp16, masked, swizzled) ----
    #pragma unroll
    for (int it = 0; it < 8; ++it) {
        int idx = it * 256 + tid;          // 2048 items: 128 rows x 16 kgroups
        int row = idx >> 4;
        int kg  = idx & 15;
        int n   = n0 + row;
        float nf = (float)n;
        float m  = (n < L) ? 0.125f : 0.0f;  // amp 1/sqrt(K) fused with mask

        unsigned hi[4];
        #pragma unroll
        for (int j = 0; j < 4; ++j) {
            int k = kg * 4 + j + 1;
            float Delta = (TWO_PI_F * (float)k) / Lf;
            float theta = nf * Delta;
            float q = rintf(theta * INV_2PI);
            float r = fmaf(-q, PI2_HI, theta);
            r       = fmaf(-q, PI2_LO, r);
            float s, c;
            __sincosf(r, &s, &c);
            hi[j] = packh2(__float2half_rn(c * m), __float2half_rn(s * m));
        }
        *reinterpret_cast<uint4*>(smem + SMEM_A + sw((unsigned)row, (unsigned)kg * 16)) =
            make_uint4(hi[0], hi[1], hi[2], hi[3]);
    }

    // ---- Per-thread ldmatrix address components ----
    const unsigned m0    = (unsigned)wid * 16u;
    const unsigned aRow  = m0 + (unsigned)(lane & 15);
    const unsigned aXr   = (aRow & 7u) << 4;
    const unsigned aC0   = (unsigned)(lane & 16);          // 0 or 16 bytes
    const uint32_t aBase = sb + SMEM_A + aRow * 256u;
    const unsigned bRl = (unsigned)((lane & 7) + ((lane & 16) ? 8 : 0));
    const unsigned bXr = (bRl & 7u) << 4;
    const unsigned bC0 = (unsigned)((lane & 8) ? 16 : 0);

    __syncthreads();   // A tile ready

    for (int nt = 0; nt < NT; ++nt) {
        CP_ASYNC_WAIT0();
        __syncthreads();   // B tile nt ready; all warps done with the other buffer

        if (nt + 1 < NT) {
            const unsigned char* gBn = g_B + (size_t)(nt + 1) * 32768;
            uint32_t bo = sb + SMEM_B + (unsigned)((nt + 1) & 1) * 32768u;
            #pragma unroll
            for (int it = 0; it < 8; ++it)
                CP_ASYNC16(bo + it * 4096 + tid * 16, gBn + it * 4096 + tid * 16);
            CP_ASYNC_COMMIT();
        }

        const uint32_t bBase = sb + SMEM_B + (unsigned)(nt & 1) * 32768u;

        float acc[16][4];
        #pragma unroll
        for (int i = 0; i < 16; ++i)
            #pragma unroll
            for (int j = 0; j < 4; ++j) acc[i][j] = 0.0f;

        #pragma unroll
        for (int ks = 0; ks < 8; ++ks) {
            uint32_t ah[4];
            LDSM_X4(ah, aBase + (((unsigned)ks * 32u + aC0) ^ aXr));

            const unsigned bkb = ((unsigned)ks * 32u + bC0) ^ bXr;
            #pragma unroll
            for (int np = 0; np < 8; ++np) {
                uint32_t bh[4];
                LDSM_X4(bh, bBase + (np * 16u + bRl) * 256u + bkb);
                MMA16816(acc[2 * np],     ah, bh[0], bh[1]);
                MMA16816(acc[2 * np + 1], ah, bh[2], bh[3]);
            }
        }

        // ---- Epilogue: registers -> gmem (full 32B sectors) ----
        const int r0 = lane >> 2;
        const int c0 = (lane & 3) * 2;
        size_t ob = ((size_t)(mtile * 128) + m0) * DDIM + (size_t)nt * 128;
        #pragma unroll
        for (int t8 = 0; t8 < 16; ++t8) {
            float2 v0 = make_float2(acc[t8][0], acc[t8][1]);
            float2 v1 = make_float2(acc[t8][2], acc[t8][3]);
            *reinterpret_cast<float2*>(&out[ob + (size_t)r0 * DDIM + t8 * 8 + c0])       = v0;
            *reinterpret_cast<float2*>(&out[ob + (size_t)(r0 + 8) * DDIM + t8 * 8 + c0]) = v1;
        }
    }
}

// ---------------------------------------------------------------------------
// Mask tail output (only if the harness output includes it)
// ---------------------------------------------------------------------------
__global__ void mask_kernel(const int* __restrict__ lengths, float* __restrict__ mask_out)
{
    int idx = blockIdx.x * blockDim.x + threadIdx.x;
    int b = idx >> 13;
    int n = idx & (NMAX - 1);
    mask_out[idx] = (n < lengths[b]) ? 1.0f : 0.0f;
}

// ---------------------------------------------------------------------------
extern "C" void kernel_launch(void* const* d_in, const int* in_sizes, int n_in,
                              void* d_out, int out_size)
{
    const int*   lengths = (const int*)d_in[0];
    const float* W       = (const float*)d_in[1];
    float*       out     = (float*)d_out;
    (void)in_sizes; (void)n_in;

    cudaFuncSetAttribute(gemm_kernel,
                         cudaFuncAttributeMaxDynamicSharedMemorySize, SMEM_TOTAL);

    wprep_kernel<<<64, 256>>>(W);
    gemm_kernel<<<MT, 256, SMEM_TOTAL>>>(lengths, out);

    long long pos_elems = (long long)MTOT * DDIM;
    if ((long long)out_size >= pos_elems + (long long)MTOT) {
        mask_kernel<<<MTOT / 256, 256>>>(lengths, out + pos_elems);
    }
}

// round 8
// speedup vs baseline: 7.4760x; 1.0053x over previous
#include <cuda_runtime.h>
#include <cuda_fp16.h>
#include <cstdint>

// ---------------------------------------------------------------------------
// Problem constants
// ---------------------------------------------------------------------------
#define BATCH 16
#define DDIM  1024
#define NMAX  8192
#define MTOT  (BATCH * NMAX)     // 131072 rows
#define MT    1024               // M tiles of 128 rows
#define NT    8                  // N tiles of 128 cols

// fp32 constants mirroring the reference's fp32 math
#define TWO_PI_F 6.28318548202514648438f
#define PI2_HI   6.28318548202514648438f
#define PI2_LO  -1.74845553e-7f
#define INV_2PI  0.15915494309189535f

// W images: per ntile 32KB (128 d-rows x 128 fp16, swizzled 256B rows). 256KB, L2-resident.
__device__ __align__(1024) static unsigned char g_B[(size_t)NT * 32768];

// ---------------------------------------------------------------------------
// Helpers
// ---------------------------------------------------------------------------
__device__ __forceinline__ uint32_t smem_u32(const void* p) {
    uint32_t a;
    asm("{ .reg .u64 t; cvta.to.shared.u64 t, %1; cvt.u32.u64 %0, t; }" : "=r"(a) : "l"(p));
    return a;
}

// Swizzled byte offset inside a 128x128 fp16 tile (256B rows):
// XOR the 16B-chunk index with (row & 7) -> conflict-free ldmatrix.
__device__ __forceinline__ unsigned sw(unsigned row, unsigned kb) {
    return row * 256u + (kb ^ ((row & 7u) << 4));
}

__device__ __forceinline__ unsigned packh2(__half a, __half b) {
    return (unsigned)__half_as_ushort(a) | ((unsigned)__half_as_ushort(b) << 16);
}

#define CP_ASYNC16(sm, gp) \
    asm volatile("cp.async.cg.shared.global [%0], [%1], 16;" :: "r"(sm), "l"(gp))
#define CP_ASYNC_COMMIT() asm volatile("cp.async.commit_group;" ::: "memory")
#define CP_ASYNC_WAIT0()  asm volatile("cp.async.wait_group 0;" ::: "memory")

#define LDSM_X4(r, addr) \
    asm volatile("ldmatrix.sync.aligned.m8n8.x4.shared.b16 {%0,%1,%2,%3}, [%4];" \
        : "=r"((r)[0]), "=r"((r)[1]), "=r"((r)[2]), "=r"((r)[3]) : "r"(addr))

#define MMA16816(c, a, b0v, b1v) \
    asm volatile("mma.sync.aligned.m16n8k16.row.col.f32.f16.f16.f32 " \
        "{%0,%1,%2,%3}, {%4,%5,%6,%7}, {%8,%9}, {%0,%1,%2,%3};" \
        : "+f"((c)[0]), "+f"((c)[1]), "+f"((c)[2]), "+f"((c)[3]) \
        : "r"((a)[0]), "r"((a)[1]), "r"((a)[2]), "r"((a)[3]), "r"(b0v), "r"(b1v))

// Streaming (evict-first) stores: output is write-once, never re-read.
#define STG_CS_V2(ptr, x, y) \
    asm volatile("st.global.cs.v2.f32 [%0], {%1, %2};" :: "l"(ptr), "f"(x), "f"(y) : "memory")
#define STG_CS_V4(ptr, a, bb, c, d) \
    asm volatile("st.global.cs.v4.b32 [%0], {%1, %2, %3, %4};" \
        :: "l"(ptr), "r"(a), "r"(bb), "r"(c), "r"(d) : "memory")

// ---------------------------------------------------------------------------
// W prep: W[1024,128] fp32 -> fp16, swizzled per-ntile tile images
// ---------------------------------------------------------------------------
__global__ void __launch_bounds__(256) wprep_kernel(const float* __restrict__ W)
{
    int idx  = blockIdx.x * 256 + threadIdx.x;     // < 8*128*16 = 16384
    int nt   = idx >> 11;
    int rem  = idx & 2047;
    int drow = rem >> 4;
    int kg   = rem & 15;

    const float* wr = W + (size_t)(nt * 128 + drow) * 128 + kg * 8;
    unsigned hi[4];
    #pragma unroll
    for (int j = 0; j < 4; ++j)
        hi[j] = packh2(__float2half_rn(wr[2 * j]), __float2half_rn(wr[2 * j + 1]));
    unsigned char* base = g_B + (size_t)nt * 32768;
    *reinterpret_cast<uint4*>(base + sw((unsigned)drow, (unsigned)kg * 16)) =
        make_uint4(hi[0], hi[1], hi[2], hi[3]);
}

// ---------------------------------------------------------------------------
// Fused gen + GEMM kernel. Single-pass fp16. 2 CTAs/SM.
// N-tile order is staggered per-CTA to desynchronize DRAM store bursts.
// smem: A [0,32K), B buf0 [32K,64K), B buf1 [64K,96K)
// ---------------------------------------------------------------------------
#define SMEM_A     0
#define SMEM_B     32768
#define SMEM_TOTAL 98304

__global__ void __launch_bounds__(256, 2)
gemm_kernel(const int* __restrict__ lengths, float* __restrict__ out)
{
    extern __shared__ unsigned char smem[];
    const uint32_t sb = smem_u32(smem);
    const int tid  = threadIdx.x;
    const int lane = tid & 31;
    const int wid  = tid >> 5;

    const int mtile = blockIdx.x;          // 0..1023
    const int b     = mtile >> 6;
    const int n0    = (mtile & 63) * 128;
    const int phase = (mtile & 3) * 2;     // stagger N-tile schedule across CTAs

    const int   L  = lengths[b];
    const float Lf = (float)L;

    // ---- Fast path: fully-masked tile -> pure zero fill, no compute ----
    if (n0 >= L) {
        float* base = out + (size_t)mtile * 128 * DDIM;
        #pragma unroll 4
        for (int i = tid; i < (128 * DDIM) / 4; i += 256)
            STG_CS_V4(base + (size_t)i * 4, 0u, 0u, 0u, 0u);
        return;
    }

    // ---- Prologue: async-copy first B tile (starts before gen) ----
    {
        const unsigned char* gB0 = g_B + (size_t)phase * 32768;
        #pragma unroll
        for (int it = 0; it < 8; ++it)
            CP_ASYNC16(sb + SMEM_B + it * 4096 + tid * 16, gB0 + it * 4096 + tid * 16);
        CP_ASYNC_COMMIT();
    }

    // ---- Generate feats tile (fp16, masked, swizzled) ----
    #pragma unroll
    for (int it = 0; it < 8; ++it) {
        int idx = it * 256 + tid;          // 2048 items: 128 rows x 16 kgroups
        int row = idx >> 4;
        int kg  = idx & 15;
        int n   = n0 + row;
        float nf = (float)n;
        float m  = (n < L) ? 0.125f : 0.0f;  // amp 1/sqrt(K) fused with mask

        unsigned hi[4];
        #pragma unroll
        for (int j = 0; j < 4; ++j) {
            int k = kg * 4 + j + 1;
            float Delta = (TWO_PI_F * (float)k) / Lf;
            float theta = nf * Delta;
            float q = rintf(theta * INV_2PI);
            float r = fmaf(-q, PI2_HI, theta);
            r       = fmaf(-q, PI2_LO, r);
            float s, c;
            __sincosf(r, &s, &c);
            hi[j] = packh2(__float2half_rn(c * m), __float2half_rn(s * m));
        }
        *reinterpret_cast<uint4*>(smem + SMEM_A + sw((unsigned)row, (unsigned)kg * 16)) =
            make_uint4(hi[0], hi[1], hi[2], hi[3]);
    }

    // ---- Per-thread ldmatrix address components ----
    const unsigned m0    = (unsigned)wid * 16u;
    const unsigned aRow  = m0 + (unsigned)(lane & 15);
    const unsigned aXr   = (aRow & 7u) << 4;
    const unsigned aC0   = (unsigned)(lane & 16);          // 0 or 16 bytes
    const uint32_t aBase = sb + SMEM_A + aRow * 256u;
    const unsigned bRl = (unsigned)((lane & 7) + ((lane & 16) ? 8 : 0));
    const unsigned bXr = (bRl & 7u) << 4;
    const unsigned bC0 = (unsigned)((lane & 8) ? 16 : 0);

    __syncthreads();   // A tile ready

    for (int it = 0; it < NT; ++it) {
        const int nt = (it + phase) & 7;   // actual N-tile index this iteration

        CP_ASYNC_WAIT0();
        __syncthreads();   // B tile ready; all warps done with the other buffer

        if (it + 1 < NT) {
            const unsigned char* gBn = g_B + (size_t)(((it + 1 + phase) & 7)) * 32768;
            uint32_t bo = sb + SMEM_B + (unsigned)((it + 1) & 1) * 32768u;
            #pragma unroll
            for (int i2 = 0; i2 < 8; ++i2)
                CP_ASYNC16(bo + i2 * 4096 + tid * 16, gBn + i2 * 4096 + tid * 16);
            CP_ASYNC_COMMIT();
        }

        const uint32_t bBase = sb + SMEM_B + (unsigned)(it & 1) * 32768u;

        float acc[16][4];
        #pragma unroll
        for (int i = 0; i < 16; ++i)
            #pragma unroll
            for (int j = 0; j < 4; ++j) acc[i][j] = 0.0f;

        #pragma unroll
        for (int ks = 0; ks < 8; ++ks) {
            uint32_t ah[4];
            LDSM_X4(ah, aBase + (((unsigned)ks * 32u + aC0) ^ aXr));

            const unsigned bkb = ((unsigned)ks * 32u + bC0) ^ bXr;
            #pragma unroll
            for (int np = 0; np < 8; ++np) {
                uint32_t bh[4];
                LDSM_X4(bh, bBase + (np * 16u + bRl) * 256u + bkb);
                MMA16816(acc[2 * np],     ah, bh[0], bh[1]);
                MMA16816(acc[2 * np + 1], ah, bh[2], bh[3]);
            }
        }

        // ---- Epilogue: registers -> gmem, streaming stores (full 32B sectors) ----
        const int r0 = lane >> 2;
        const int c0 = (lane & 3) * 2;
        size_t ob = ((size_t)(mtile * 128) + m0) * DDIM + (size_t)nt * 128;
        #pragma unroll
        for (int t8 = 0; t8 < 16; ++t8) {
            STG_CS_V2(&out[ob + (size_t)r0 * DDIM + t8 * 8 + c0],       acc[t8][0], acc[t8][1]);
            STG_CS_V2(&out[ob + (size_t)(r0 + 8) * DDIM + t8 * 8 + c0], acc[t8][2], acc[t8][3]);
        }
    }
}

// ---------------------------------------------------------------------------
// Mask tail output (only if the harness output includes it)
// ---------------------------------------------------------------------------
__global__ void mask_kernel(const int* __restrict__ lengths, float* __restrict__ mask_out)
{
    int idx = blockIdx.x * blockDim.x + threadIdx.x;
    int b = idx >> 13;
    int n = idx & (NMAX - 1);
    mask_out[idx] = (n < lengths[b]) ? 1.0f : 0.0f;
}

// ---------------------------------------------------------------------------
extern "C" void kernel_launch(void* const* d_in, const int* in_sizes, int n_in,
                              void* d_out, int out_size)
{
    const int*   lengths = (const int*)d_in[0];
    const float* W       = (const float*)d_in[1];
    float*       out     = (float*)d_out;
    (void)in_sizes; (void)n_in;

    cudaFuncSetAttribute(gemm_kernel,
                         cudaFuncAttributeMaxDynamicSharedMemorySize, SMEM_TOTAL);

    wprep_kernel<<<64, 256>>>(W);
    gemm_kernel<<<MT, 256, SMEM_TOTAL>>>(lengths, out);

    long long pos_elems = (long long)MTOT * DDIM;
    if ((long long)out_size >= pos_elems + (long long)MTOT) {
        mask_kernel<<<MTOT / 256, 256>>>(lengths, out + pos_elems);
    }
}

// round 9
// speedup vs baseline: 8.2561x; 1.1044x over previous
#include <cuda_runtime.h>
#include <cuda_fp16.h>
#include <cstdint>

// ---------------------------------------------------------------------------
// Problem constants
// ---------------------------------------------------------------------------
#define BATCH 16
#define DDIM  1024
#define NMAX  8192
#define MTOT  (BATCH * NMAX)     // 131072 rows
#define MT    1024               // M tiles of 128 rows
#define NT    8                  // N tiles of 128 cols

// fp32 constants mirroring the reference's fp32 math
#define TWO_PI_F 6.28318548202514648438f
#define PI2_HI   6.28318548202514648438f
#define PI2_LO  -1.74845553e-7f
#define INV_2PI  0.15915494309189535f

// W images: per ntile 32KB (128 d-rows x 128 fp16, swizzled 256B rows). 256KB, L2-resident.
__device__ __align__(1024) static unsigned char g_B[(size_t)NT * 32768];

// ---------------------------------------------------------------------------
// Helpers
// ---------------------------------------------------------------------------
__device__ __forceinline__ uint32_t smem_u32(const void* p) {
    uint32_t a;
    asm("{ .reg .u64 t; cvta.to.shared.u64 t, %1; cvt.u32.u64 %0, t; }" : "=r"(a) : "l"(p));
    return a;
}

// Swizzled byte offset inside a 128x128 fp16 tile (256B rows):
// XOR the 16B-chunk index with (row & 7) -> conflict-free ldmatrix.
__device__ __forceinline__ unsigned sw(unsigned row, unsigned kb) {
    return row * 256u + (kb ^ ((row & 7u) << 4));
}

__device__ __forceinline__ unsigned packh2(__half a, __half b) {
    return (unsigned)__half_as_ushort(a) | ((unsigned)__half_as_ushort(b) << 16);
}

#define CP_ASYNC16(sm, gp) \
    asm volatile("cp.async.cg.shared.global [%0], [%1], 16;" :: "r"(sm), "l"(gp))
#define CP_ASYNC_COMMIT() asm volatile("cp.async.commit_group;" ::: "memory")
#define CP_ASYNC_WAIT0()  asm volatile("cp.async.wait_group 0;" ::: "memory")

#define LDSM_X4(r, addr) \
    asm volatile("ldmatrix.sync.aligned.m8n8.x4.shared.b16 {%0,%1,%2,%3}, [%4];" \
        : "=r"((r)[0]), "=r"((r)[1]), "=r"((r)[2]), "=r"((r)[3]) : "r"(addr))

#define MMA16816(c, a, b0v, b1v) \
    asm volatile("mma.sync.aligned.m16n8k16.row.col.f32.f16.f16.f32 " \
        "{%0,%1,%2,%3}, {%4,%5,%6,%7}, {%8,%9}, {%0,%1,%2,%3};" \
        : "+f"((c)[0]), "+f"((c)[1]), "+f"((c)[2]), "+f"((c)[3]) \
        : "r"((a)[0]), "r"((a)[1]), "r"((a)[2]), "r"((a)[3]), "r"(b0v), "r"(b1v))

// Streaming (evict-first) stores: output is write-once, never re-read.
#define STG_CS_V2(ptr, x, y) \
    asm volatile("st.global.cs.v2.f32 [%0], {%1, %2};" :: "l"(ptr), "f"(x), "f"(y) : "memory")
#define STG_CS_V4Z(ptr) \
    asm volatile("st.global.cs.v4.b32 [%0], {%1, %1, %1, %1};" :: "l"(ptr), "r"(0u) : "memory")

// ---------------------------------------------------------------------------
// W prep: W[1024,128] fp32 -> fp16, swizzled per-ntile tile images
// ---------------------------------------------------------------------------
__global__ void __launch_bounds__(256) wprep_kernel(const float* __restrict__ W)
{
    int idx  = blockIdx.x * 256 + threadIdx.x;     // < 8*128*16 = 16384
    int nt   = idx >> 11;
    int rem  = idx & 2047;
    int drow = rem >> 4;
    int kg   = rem & 15;

    const float* wr = W + (size_t)(nt * 128 + drow) * 128 + kg * 8;
    unsigned hi[4];
    #pragma unroll
    for (int j = 0; j < 4; ++j)
        hi[j] = packh2(__float2half_rn(wr[2 * j]), __float2half_rn(wr[2 * j + 1]));
    unsigned char* base = g_B + (size_t)nt * 32768;
    *reinterpret_cast<uint4*>(base + sw((unsigned)drow, (unsigned)kg * 16)) =
        make_uint4(hi[0], hi[1], hi[2], hi[3]);
}

// ---------------------------------------------------------------------------
// Fused gen + GEMM kernel. Single-pass fp16. 2 CTAs/SM. 32x64 warp tiles.
// Gen uses a rotation recurrence: 8 sincos pairs/thread instead of 32 (MUFU 4x cut).
// smem: A [0,32K), B buf0 [32K,64K), B buf1 [64K,96K)
// ---------------------------------------------------------------------------
#define SMEM_A     0
#define SMEM_B     32768
#define SMEM_TOTAL 98304

__global__ void __launch_bounds__(256, 2)
gemm_kernel(const int* __restrict__ lengths, float* __restrict__ out)
{
    extern __shared__ unsigned char smem[];
    const uint32_t sb = smem_u32(smem);
    const int tid  = threadIdx.x;
    const int lane = tid & 31;
    const int wid  = tid >> 5;

    const int mtile = blockIdx.x;          // 0..1023
    const int b     = mtile >> 6;
    const int n0    = (mtile & 63) * 128;
    const int phase = (mtile & 3) * 2;     // stagger N-tile schedule across CTAs

    const int   L  = lengths[b];
    const float Lf = (float)L;

    // ---- Fast path: fully-masked tile -> pure zero fill, no compute ----
    if (n0 >= L) {
        float* base = out + (size_t)mtile * 128 * DDIM;
        #pragma unroll 4
        for (int i = tid; i < (128 * DDIM) / 4; i += 256)
            STG_CS_V4Z(base + (size_t)i * 4);
        return;
    }

    // ---- Prologue: async-copy first B tile (starts before gen) ----
    {
        const unsigned char* gB0 = g_B + (size_t)phase * 32768;
        #pragma unroll
        for (int it = 0; it < 8; ++it)
            CP_ASYNC16(sb + SMEM_B + it * 4096 + tid * 16, gB0 + it * 4096 + tid * 16);
        CP_ASYNC_COMMIT();
    }

    // ---- Generate feats tile (fp16, masked, swizzled) via rotation recurrence ----
    {
        const int row0 = tid >> 4;         // 0..15
        const int kg   = tid & 15;
        const float nf = (float)(n0 + row0);

        float c[4], s[4], C[4], S[4];
        #pragma unroll
        for (int j = 0; j < 4; ++j) {
            int k = kg * 4 + j + 1;
            float Delta = (TWO_PI_F * (float)k) / Lf;
            // initial angle: exact 2*pi range reduction of fl(n * Delta)
            float theta = nf * Delta;
            float q = rintf(theta * INV_2PI);
            float r = fmaf(-q, PI2_HI, theta);
            r       = fmaf(-q, PI2_LO, r);
            __sincosf(r, &s[j], &c[j]);
            // step rotation by 16*Delta (<= 1.571 rad for L >= 4096, k <= 64)
            __sincosf(16.0f * Delta, &S[j], &C[j]);
        }

        #pragma unroll
        for (int it = 0; it < 8; ++it) {
            int row = row0 + it * 16;
            int n   = n0 + row;
            float m = (n < L) ? 0.125f : 0.0f;   // amp 1/sqrt(K) fused with mask
            unsigned hi[4];
            #pragma unroll
            for (int j = 0; j < 4; ++j)
                hi[j] = packh2(__float2half_rn(c[j] * m), __float2half_rn(s[j] * m));
            *reinterpret_cast<uint4*>(smem + SMEM_A + sw((unsigned)row, (unsigned)kg * 16)) =
                make_uint4(hi[0], hi[1], hi[2], hi[3]);
            #pragma unroll
            for (int j = 0; j < 4; ++j) {
                float cn = fmaf(c[j], C[j], -s[j] * S[j]);
                float sn = fmaf(s[j], C[j],  c[j] * S[j]);
                c[j] = cn; s[j] = sn;
            }
        }
    }

    // ---- Per-thread ldmatrix address components (warp tile 32 rows x 64 cols) ----
    const unsigned m0 = (unsigned)(wid >> 1) * 32u;   // warp M base (0,32,64,96)
    const unsigned nb = (unsigned)(wid & 1) * 64u;    // warp N base (0,64)
    const unsigned aRow  = m0 + (unsigned)(lane & 15);
    const unsigned aXr   = (aRow & 7u) << 4;          // same for aRow+16
    const unsigned aC0   = (unsigned)(lane & 16);     // 0 or 16 bytes
    const uint32_t aBase0 = sb + SMEM_A + aRow * 256u;
    const uint32_t aBase1 = aBase0 + 16u * 256u;
    const unsigned bRl = (unsigned)((lane & 7) + ((lane & 16) ? 8 : 0));
    const unsigned bXr = (bRl & 7u) << 4;
    const unsigned bC0 = (unsigned)((lane & 8) ? 16 : 0);

    __syncthreads();   // A tile ready

    for (int it = 0; it < NT; ++it) {
        const int nt = (it + phase) & 7;   // actual N-tile index this iteration

        CP_ASYNC_WAIT0();
        __syncthreads();   // B tile ready; all warps done with the other buffer

        if (it + 1 < NT) {
            const unsigned char* gBn = g_B + (size_t)(((it + 1 + phase) & 7)) * 32768;
            uint32_t bo = sb + SMEM_B + (unsigned)((it + 1) & 1) * 32768u;
            #pragma unroll
            for (int i2 = 0; i2 < 8; ++i2)
                CP_ASYNC16(bo + i2 * 4096 + tid * 16, gBn + i2 * 4096 + tid * 16);
            CP_ASYNC_COMMIT();
        }

        const uint32_t bBase = sb + SMEM_B + (unsigned)(it & 1) * 32768u;

        // acc[0..7]: m-frag 0 (rows m0..m0+15), acc[8..15]: m-frag 1 (rows +16)
        float acc[16][4];
        #pragma unroll
        for (int i = 0; i < 16; ++i)
            #pragma unroll
            for (int j = 0; j < 4; ++j) acc[i][j] = 0.0f;

        #pragma unroll
        for (int ks = 0; ks < 8; ++ks) {
            const unsigned akb = ((unsigned)ks * 32u + aC0) ^ aXr;
            uint32_t a0[4], a1[4];
            LDSM_X4(a0, aBase0 + akb);
            LDSM_X4(a1, aBase1 + akb);

            const unsigned bkb = ((unsigned)ks * 32u + bC0) ^ bXr;
            #pragma unroll
            for (int np = 0; np < 4; ++np) {
                uint32_t bh[4];
                LDSM_X4(bh, bBase + (nb + np * 16u + bRl) * 256u + bkb);
                MMA16816(acc[np * 2],         a0, bh[0], bh[1]);
                MMA16816(acc[np * 2 + 1],     a0, bh[2], bh[3]);
                MMA16816(acc[8 + np * 2],     a1, bh[0], bh[1]);
                MMA16816(acc[8 + np * 2 + 1], a1, bh[2], bh[3]);
            }
        }

        // ---- Epilogue: registers -> gmem, streaming stores ----
        const int r0 = lane >> 2;
        const int c0 = (lane & 3) * 2;
        size_t ob = ((size_t)(mtile * 128) + m0) * DDIM + (size_t)nt * 128 + nb;
        #pragma unroll
        for (int t8 = 0; t8 < 8; ++t8) {
            STG_CS_V2(&out[ob + (size_t)r0 * DDIM + t8 * 8 + c0],       acc[t8][0], acc[t8][1]);
            STG_CS_V2(&out[ob + (size_t)(r0 + 8) * DDIM + t8 * 8 + c0], acc[t8][2], acc[t8][3]);
        }
        size_t ob2 = ob + 16u * DDIM;
        #pragma unroll
        for (int t8 = 0; t8 < 8; ++t8) {
            STG_CS_V2(&out[ob2 + (size_t)r0 * DDIM + t8 * 8 + c0],       acc[8 + t8][0], acc[8 + t8][1]);
            STG_CS_V2(&out[ob2 + (size_t)(r0 + 8) * DDIM + t8 * 8 + c0], acc[8 + t8][2], acc[8 + t8][3]);
        }
    }
}

// ---------------------------------------------------------------------------
// Mask tail output (only if the harness output includes it)
// ---------------------------------------------------------------------------
__global__ void mask_kernel(const int* __restrict__ lengths, float* __restrict__ mask_out)
{
    int idx = blockIdx.x * blockDim.x + threadIdx.x;
    int b = idx >> 13;
    int n = idx & (NMAX - 1);
    mask_out[idx] = (n < lengths[b]) ? 1.0f : 0.0f;
}

// ---------------------------------------------------------------------------
extern "C" void kernel_launch(void* const* d_in, const int* in_sizes, int n_in,
                              void* d_out, int out_size)
{
    const int*   lengths = (const int*)d_in[0];
    const float* W       = (const float*)d_in[1];
    float*       out     = (float*)d_out;
    (void)in_sizes; (void)n_in;

    cudaFuncSetAttribute(gemm_kernel,
                         cudaFuncAttributeMaxDynamicSharedMemorySize, SMEM_TOTAL);

    wprep_kernel<<<64, 256>>>(W);
    gemm_kernel<<<MT, 256, SMEM_TOTAL>>>(lengths, out);

    long long pos_elems = (long long)MTOT * DDIM;
    if ((long long)out_size >= pos_elems + (long long)MTOT) {
        mask_kernel<<<MTOT / 256, 256>>>(lengths, out + pos_elems);
    }
}

// round 11
// speedup vs baseline: 8.3846x; 1.0156x over previous
#include <cuda_runtime.h>
#include <cuda_fp16.h>
#include <cstdint>

// ---------------------------------------------------------------------------
// Problem constants
// ---------------------------------------------------------------------------
#define BATCH 16
#define DDIM  1024
#define NMAX  8192
#define MTOT  (BATCH * NMAX)     // 131072 rows
#define MT    1024               // M tiles of 128 rows
#define NT    8                  // N tiles of 128 cols

// fp32 constants mirroring the reference's fp32 math
#define TWO_PI_F 6.28318548202514648438f
#define PI2_HI   6.28318548202514648438f
#define PI2_LO  -1.74845553e-7f
#define INV_2PI  0.15915494309189535f

// W images: per ntile 32KB (128 d-rows x 128 fp16, swizzled 256B rows). 256KB, L2-resident.
__device__ __align__(1024) static unsigned char g_B[(size_t)NT * 32768];

// ---------------------------------------------------------------------------
// Helpers
// ---------------------------------------------------------------------------
__device__ __forceinline__ uint32_t smem_u32(const void* p) {
    uint32_t a;
    asm("{ .reg .u64 t; cvta.to.shared.u64 t, %1; cvt.u32.u64 %0, t; }" : "=r"(a) : "l"(p));
    return a;
}

// Swizzled byte offset inside a 128x128 fp16 tile (256B rows):
// XOR the 16B-chunk index with (row & 7) -> conflict-free ldmatrix.
__device__ __forceinline__ unsigned sw(unsigned row, unsigned kb) {
    return row * 256u + (kb ^ ((row & 7u) << 4));
}

__device__ __forceinline__ unsigned packh2(__half a, __half b) {
    return (unsigned)__half_as_ushort(a) | ((unsigned)__half_as_ushort(b) << 16);
}

#define CP_ASYNC16(sm, gp) \
    asm volatile("cp.async.cg.shared.global [%0], [%1], 16;" :: "r"(sm), "l"(gp))
#define CP_ASYNC_COMMIT() asm volatile("cp.async.commit_group;" ::: "memory")
#define CP_ASYNC_WAIT0()  asm volatile("cp.async.wait_group 0;" ::: "memory")

#define LDSM_X4(r, addr) \
    asm volatile("ldmatrix.sync.aligned.m8n8.x4.shared.b16 {%0,%1,%2,%3}, [%4];" \
        : "=r"((r)[0]), "=r"((r)[1]), "=r"((r)[2]), "=r"((r)[3]) : "r"(addr))

#define MMA16816(c, a, b0v, b1v) \
    asm volatile("mma.sync.aligned.m16n8k16.row.col.f32.f16.f16.f32 " \
        "{%0,%1,%2,%3}, {%4,%5,%6,%7}, {%8,%9}, {%0,%1,%2,%3};" \
        : "+f"((c)[0]), "+f"((c)[1]), "+f"((c)[2]), "+f"((c)[3]) \
        : "r"((a)[0]), "r"((a)[1]), "r"((a)[2]), "r"((a)[3]), "r"(b0v), "r"(b1v))

// Streaming (evict-first) stores: output is write-once, never re-read.
#define STG_CS_V2(ptr, x, y) \
    asm volatile("st.global.cs.v2.f32 [%0], {%1, %2};" :: "l"(ptr), "f"(x), "f"(y) : "memory")
#define STG_CS_V4Z(ptr) \
    asm volatile("st.global.cs.v4.b32 [%0], {%1, %1, %1, %1};" :: "l"(ptr), "r"(0u) : "memory")

// ---------------------------------------------------------------------------
// W prep: W[1024,128] fp32 -> fp16, swizzled per-ntile tile images
// ---------------------------------------------------------------------------
__global__ void __launch_bounds__(256) wprep_kernel(const float* __restrict__ W)
{
    int idx  = blockIdx.x * 256 + threadIdx.x;     // < 8*128*16 = 16384
    int nt   = idx >> 11;
    int rem  = idx & 2047;
    int drow = rem >> 4;
    int kg   = rem & 15;

    const float* wr = W + (size_t)(nt * 128 + drow) * 128 + kg * 8;
    unsigned hi[4];
    #pragma unroll
    for (int j = 0; j < 4; ++j)
        hi[j] = packh2(__float2half_rn(wr[2 * j]), __float2half_rn(wr[2 * j + 1]));
    unsigned char* base = g_B + (size_t)nt * 32768;
    *reinterpret_cast<uint4*>(base + sw((unsigned)drow, (unsigned)kg * 16)) =
        make_uint4(hi[0], hi[1], hi[2], hi[3]);
}

// ---------------------------------------------------------------------------
// Fused gen + GEMM (+ mask tail) kernel. Single-pass fp16. 2 CTAs/SM.
// N-tile phase = mtile & 7: co-resident CTAs (bid, bid+148) differ by 4 tiles
// (148 mod 8 = 4), so one CTA's MMA phase overlaps the other's store phase.
// smem: A [0,32K), B buf0 [32K,64K), B buf1 [64K,96K)
// ---------------------------------------------------------------------------
#define SMEM_A     0
#define SMEM_B     32768
#define SMEM_TOTAL 98304

__global__ void __launch_bounds__(256, 2)
gemm_kernel(const int* __restrict__ lengths, float* __restrict__ out,
            float* __restrict__ mask_out)
{
    extern __shared__ unsigned char smem[];
    const uint32_t sb = smem_u32(smem);
    const int tid  = threadIdx.x;
    const int lane = tid & 31;
    const int wid  = tid >> 5;

    const int mtile = blockIdx.x;          // 0..1023
    const int b     = mtile >> 6;
    const int n0    = (mtile & 63) * 128;
    const int phase = mtile & 7;           // desync co-resident CTAs (148 % 8 == 4)

    const int   L  = lengths[b];
    const float Lf = (float)L;

    // ---- Mask tail for this tile's 128 rows (fused; one float per thread<128) ----
    if (mask_out != nullptr && tid < 128) {
        int n = n0 + tid;
        mask_out[(size_t)mtile * 128 + tid] = (n < L) ? 1.0f : 0.0f;
    }

    // ---- Fast path: fully-masked tile -> pure zero fill, no compute ----
    if (n0 >= L) {
        float* base = out + (size_t)mtile * 128 * DDIM;
        #pragma unroll 4
        for (int i = tid; i < (128 * DDIM) / 4; i += 256)
            STG_CS_V4Z(base + (size_t)i * 4);
        return;
    }

    // ---- Prologue: async-copy first B tile (starts before gen) ----
    {
        const unsigned char* gB0 = g_B + (size_t)phase * 32768;
        #pragma unroll
        for (int it = 0; it < 8; ++it)
            CP_ASYNC16(sb + SMEM_B + it * 4096 + tid * 16, gB0 + it * 4096 + tid * 16);
        CP_ASYNC_COMMIT();
    }

    // ---- Generate feats tile (fp16, masked, swizzled) via rotation recurrence ----
    {
        const int row0 = tid >> 4;         // 0..15
        const int kg   = tid & 15;
        const float nf = (float)(n0 + row0);

        float c[4], s[4], C[4], S[4];
        #pragma unroll
        for (int j = 0; j < 4; ++j) {
            int k = kg * 4 + j + 1;
            float Delta = (TWO_PI_F * (float)k) / Lf;
            // initial angle: exact 2*pi range reduction of fl(n * Delta)
            float theta = nf * Delta;
            float q = rintf(theta * INV_2PI);
            float r = fmaf(-q, PI2_HI, theta);
            r       = fmaf(-q, PI2_LO, r);
            __sincosf(r, &s[j], &c[j]);
            // step rotation by 16*Delta (<= 1.571 rad for L >= 4096, k <= 64)
            __sincosf(16.0f * Delta, &S[j], &C[j]);
        }

        #pragma unroll
        for (int it = 0; it < 8; ++it) {
            int row = row0 + it * 16;
            int n   = n0 + row;
            float m = (n < L) ? 0.125f : 0.0f;   // amp 1/sqrt(K) fused with mask
            unsigned hi[4];
            #pragma unroll
            for (int j = 0; j < 4; ++j)
                hi[j] = packh2(__float2half_rn(c[j] * m), __float2half_rn(s[j] * m));
            *reinterpret_cast<uint4*>(smem + SMEM_A + sw((unsigned)row, (unsigned)kg * 16)) =
                make_uint4(hi[0], hi[1], hi[2], hi[3]);
            #pragma unroll
            for (int j = 0; j < 4; ++j) {
                float cn = fmaf(c[j], C[j], -s[j] * S[j]);
                float sn = fmaf(s[j], C[j],  c[j] * S[j]);
                c[j] = cn; s[j] = sn;
            }
        }
    }

    // ---- Per-thread ldmatrix address components (warp tile 32 rows x 64 cols) ----
    const unsigned m0 = (unsigned)(wid >> 1) * 32u;   // warp M base (0,32,64,96)
    const unsigned nb = (unsigned)(wid & 1) * 64u;    // warp N base (0,64)
    const unsigned aRow  = m0 + (unsigned)(lane & 15);
    const unsigned aXr   = (aRow & 7u) << 4;          // same for aRow+16
    const unsigned aC0   = (unsigned)(lane & 16);     // 0 or 16 bytes
    const uint32_t aBase0 = sb + SMEM_A + aRow * 256u;
    const uint32_t aBase1 = aBase0 + 16u * 256u;
    const unsigned bRl = (unsigned)((lane & 7) + ((lane & 16) ? 8 : 0));
    const unsigned bXr = (bRl & 7u) << 4;
    const unsigned bC0 = (unsigned)((lane & 8) ? 16 : 0);

    __syncthreads();   // A tile ready

    for (int it = 0; it < NT; ++it) {
        const int nt = (it + phase) & 7;   // actual N-tile index this iteration

        CP_ASYNC_WAIT0();
        __syncthreads();   // B tile ready; all warps done with the other buffer

        if (it + 1 < NT) {
            const unsigned char* gBn = g_B + (size_t)(((it + 1 + phase) & 7)) * 32768;
            uint32_t bo = sb + SMEM_B + (unsigned)((it + 1) & 1) * 32768u;
            #pragma unroll
            for (int i2 = 0; i2 < 8; ++i2)
                CP_ASYNC16(bo + i2 * 4096 + tid * 16, gBn + i2 * 4096 + tid * 16);
            CP_ASYNC_COMMIT();
        }

        const uint32_t bBase = sb + SMEM_B + (unsigned)(it & 1) * 32768u;

        // acc[0..7]: m-frag 0 (rows m0..m0+15), acc[8..15]: m-frag 1 (rows +16)
        float acc[16][4];
        #pragma unroll
        for (int i = 0; i < 16; ++i)
            #pragma unroll
            for (int j = 0; j < 4; ++j) acc[i][j] = 0.0f;

        #pragma unroll
        for (int ks = 0; ks < 8; ++ks) {
            const unsigned akb = ((unsigned)ks * 32u + aC0) ^ aXr;
            uint32_t a0[4], a1[4];
            LDSM_X4(a0, aBase0 + akb);
            LDSM_X4(a1, aBase1 + akb);

            const unsigned bkb = ((unsigned)ks * 32u + bC0) ^ bXr;
            #pragma unroll
            for (int np = 0; np < 4; ++np) {
                uint32_t bh[4];
                LDSM_X4(bh, bBase + (nb + np * 16u + bRl) * 256u + bkb);
                MMA16816(acc[np * 2],         a0, bh[0], bh[1]);
                MMA16816(acc[np * 2 + 1],     a0, bh[2], bh[3]);
                MMA16816(acc[8 + np * 2],     a1, bh[0], bh[1]);
                MMA16816(acc[8 + np * 2 + 1], a1, bh[2], bh[3]);
            }
        }

        // ---- Epilogue: registers -> gmem, streaming stores ----
        const int r0 = lane >> 2;
        const int c0 = (lane & 3) * 2;
        size_t ob = ((size_t)(mtile * 128) + m0) * DDIM + (size_t)nt * 128 + nb;
        #pragma unroll
        for (int t8 = 0; t8 < 8; ++t8) {
            STG_CS_V2(&out[ob + (size_t)r0 * DDIM + t8 * 8 + c0],       acc[t8][0], acc[t8][1]);
            STG_CS_V2(&out[ob + (size_t)(r0 + 8) * DDIM + t8 * 8 + c0], acc[t8][2], acc[t8][3]);
        }
        size_t ob2 = ob + 16u * DDIM;
        #pragma unroll
        for (int t8 = 0; t8 < 8; ++t8) {
            STG_CS_V2(&out[ob2 + (size_t)r0 * DDIM + t8 * 8 + c0],       acc[8 + t8][0], acc[8 + t8][1]);
            STG_CS_V2(&out[ob2 + (size_t)(r0 + 8) * DDIM + t8 * 8 + c0], acc[8 + t8][2], acc[8 + t8][3]);
        }
    }
}

// ---------------------------------------------------------------------------
extern "C" void kernel_launch(void* const* d_in, const int* in_sizes, int n_in,
                              void* d_out, int out_size)
{
    const int*   lengths = (const int*)d_in[0];
    const float* W       = (const float*)d_in[1];
    float*       out     = (float*)d_out;
    (void)in_sizes; (void)n_in;

    cudaFuncSetAttribute(gemm_kernel,
                         cudaFuncAttributeMaxDynamicSharedMemorySize, SMEM_TOTAL);

    long long pos_elems = (long long)MTOT * DDIM;
    float* mask_ptr = ((long long)out_size >= pos_elems + (long long)MTOT)
                          ? (out + pos_elems) : nullptr;

    wprep_kernel<<<64, 256>>>(W);
    gemm_kernel<<<MT, 256, SMEM_TOTAL>>>(lengths, out, mask_ptr);
}

// round 12
// speedup vs baseline: 8.4620x; 1.0092x over previous
#include <cuda_runtime.h>
#include <cuda_fp16.h>
#include <cstdint>

// ---------------------------------------------------------------------------
// Problem constants
// ---------------------------------------------------------------------------
#define BATCH 16
#define DDIM  1024
#define NMAX  8192
#define MTOT  (BATCH * NMAX)     // 131072 rows
#define MT    1024               // M tiles of 128 rows
#define NT    8                  // N tiles of 128 cols

// fp32 constants mirroring the reference's fp32 math
#define TWO_PI_F 6.28318548202514648438f
#define PI2_HI   6.28318548202514648438f
#define PI2_LO  -1.74845553e-7f
#define INV_2PI  0.15915494309189535f

// W images: per ntile 32KB (128 d-rows x 128 fp16, swizzled 256B rows). 256KB, L2-resident.
__device__ __align__(1024) static unsigned char g_B[(size_t)NT * 32768];

// ---------------------------------------------------------------------------
// Helpers
// ---------------------------------------------------------------------------
__device__ __forceinline__ uint32_t smem_u32(const void* p) {
    uint32_t a;
    asm("{ .reg .u64 t; cvta.to.shared.u64 t, %1; cvt.u32.u64 %0, t; }" : "=r"(a) : "l"(p));
    return a;
}

__device__ __forceinline__ unsigned sw(unsigned row, unsigned kb) {
    return row * 256u + (kb ^ ((row & 7u) << 4));
}

__device__ __forceinline__ unsigned packh2(__half a, __half b) {
    return (unsigned)__half_as_ushort(a) | ((unsigned)__half_as_ushort(b) << 16);
}

#define CP_ASYNC16(sm, gp) \
    asm volatile("cp.async.cg.shared.global [%0], [%1], 16;" :: "r"(sm), "l"(gp))
#define CP_ASYNC_COMMIT() asm volatile("cp.async.commit_group;" ::: "memory")
#define CP_ASYNC_WAIT0()  asm volatile("cp.async.wait_group 0;" ::: "memory")

#define LDSM_X4(r, addr) \
    asm volatile("ldmatrix.sync.aligned.m8n8.x4.shared.b16 {%0,%1,%2,%3}, [%4];" \
        : "=r"((r)[0]), "=r"((r)[1]), "=r"((r)[2]), "=r"((r)[3]) : "r"(addr))

#define MMA16816(c, a, b0v, b1v) \
    asm volatile("mma.sync.aligned.m16n8k16.row.col.f32.f16.f16.f32 " \
        "{%0,%1,%2,%3}, {%4,%5,%6,%7}, {%8,%9}, {%0,%1,%2,%3};" \
        : "+f"((c)[0]), "+f"((c)[1]), "+f"((c)[2]), "+f"((c)[3]) \
        : "r"((a)[0]), "r"((a)[1]), "r"((a)[2]), "r"((a)[3]), "r"(b0v), "r"(b1v))

#define STG_CS_V4F(ptr, a, bb, c, d) \
    asm volatile("st.global.cs.v4.f32 [%0], {%1, %2, %3, %4};" \
        :: "l"(ptr), "f"(a), "f"(bb), "f"(c), "f"(d) : "memory")
#define STG_CS_V4Z(ptr) \
    asm volatile("st.global.cs.v4.b32 [%0], {%1, %1, %1, %1};" :: "l"(ptr), "r"(0u) : "memory")

// Butterfly exchange stage: swap lane-bit K with slot-bit M over 8 float2 slots.
// Element at (lane L, slot S) moves to (L^(1<<K), S^(1<<M)) iff L_K != S_M.
template<int K, int M>
__device__ __forceinline__ void xstage(float2* v, int lane) {
    const bool hi = ((lane >> K) & 1) != 0;
    #pragma unroll
    for (int i0 = 0; i0 < 8; ++i0) {
        if (i0 & (1 << M)) continue;
        const int i1 = i0 | (1 << M);
        float sx = hi ? v[i0].x : v[i1].x;
        float sy = hi ? v[i0].y : v[i1].y;
        float rx = __shfl_xor_sync(0xffffffffu, sx, 1 << K);
        float ry = __shfl_xor_sync(0xffffffffu, sy, 1 << K);
        if (hi) { v[i0].x = rx; v[i0].y = ry; }
        else    { v[i1].x = rx; v[i1].y = ry; }
    }
}

// ---------------------------------------------------------------------------
// W prep: W[1024,128] fp32 -> fp16, swizzled per-ntile tile images
// ---------------------------------------------------------------------------
__global__ void __launch_bounds__(256) wprep_kernel(const float* __restrict__ W)
{
    int idx  = blockIdx.x * 256 + threadIdx.x;     // < 8*128*16 = 16384
    int nt   = idx >> 11;
    int rem  = idx & 2047;
    int drow = rem >> 4;
    int kg   = rem & 15;

    const float* wr = W + (size_t)(nt * 128 + drow) * 128 + kg * 8;
    unsigned hi[4];
    #pragma unroll
    for (int j = 0; j < 4; ++j)
        hi[j] = packh2(__float2half_rn(wr[2 * j]), __float2half_rn(wr[2 * j + 1]));
    unsigned char* base = g_B + (size_t)nt * 32768;
    *reinterpret_cast<uint4*>(base + sw((unsigned)drow, (unsigned)kg * 16)) =
        make_uint4(hi[0], hi[1], hi[2], hi[3]);
}

// ---------------------------------------------------------------------------
// Fused gen + GEMM (+ mask tail) kernel. Single-pass fp16. 2 CTAs/SM.
// Epilogue: 2-stage register butterfly -> STG.128 (64B/row sectors, halved wf).
// smem: A [0,32K), B buf0 [32K,64K), B buf1 [64K,96K)
// ---------------------------------------------------------------------------
#define SMEM_A     0
#define SMEM_B     32768
#define SMEM_TOTAL 98304

__global__ void __launch_bounds__(256, 2)
gemm_kernel(const int* __restrict__ lengths, float* __restrict__ out,
            float* __restrict__ mask_out)
{
    extern __shared__ unsigned char smem[];
    const uint32_t sb = smem_u32(smem);
    const int tid  = threadIdx.x;
    const int lane = tid & 31;
    const int wid  = tid >> 5;

    const int mtile = blockIdx.x;          // 0..1023
    const int b     = mtile >> 6;
    const int n0    = (mtile & 63) * 128;
    const int phase = mtile & 7;           // desync co-resident CTAs (148 % 8 == 4)

    const int   L  = lengths[b];
    const float Lf = (float)L;

    // ---- Mask tail for this tile's 128 rows (fused) ----
    if (mask_out != nullptr && tid < 128) {
        int n = n0 + tid;
        mask_out[(size_t)mtile * 128 + tid] = (n < L) ? 1.0f : 0.0f;
    }

    // ---- Fast path: fully-masked tile -> pure zero fill ----
    if (n0 >= L) {
        float* base = out + (size_t)mtile * 128 * DDIM;
        #pragma unroll 4
        for (int i = tid; i < (128 * DDIM) / 4; i += 256)
            STG_CS_V4Z(base + (size_t)i * 4);
        return;
    }

    // ---- Prologue: async-copy first B tile ----
    {
        const unsigned char* gB0 = g_B + (size_t)phase * 32768;
        #pragma unroll
        for (int it = 0; it < 8; ++it)
            CP_ASYNC16(sb + SMEM_B + it * 4096 + tid * 16, gB0 + it * 4096 + tid * 16);
        CP_ASYNC_COMMIT();
    }

    // ---- Generate feats tile (fp16, masked, swizzled) via rotation recurrence ----
    {
        const int row0 = tid >> 4;         // 0..15
        const int kg   = tid & 15;
        const float nf = (float)(n0 + row0);

        float c[4], s[4], C[4], S[4];
        #pragma unroll
        for (int j = 0; j < 4; ++j) {
            int k = kg * 4 + j + 1;
            float Delta = (TWO_PI_F * (float)k) / Lf;
            float theta = nf * Delta;
            float q = rintf(theta * INV_2PI);
            float r = fmaf(-q, PI2_HI, theta);
            r       = fmaf(-q, PI2_LO, r);
            __sincosf(r, &s[j], &c[j]);
            __sincosf(16.0f * Delta, &S[j], &C[j]);
        }

        #pragma unroll
        for (int it = 0; it < 8; ++it) {
            int row = row0 + it * 16;
            int n   = n0 + row;
            float m = (n < L) ? 0.125f : 0.0f;
            unsigned hi[4];
            #pragma unroll
            for (int j = 0; j < 4; ++j)
                hi[j] = packh2(__float2half_rn(c[j] * m), __float2half_rn(s[j] * m));
            *reinterpret_cast<uint4*>(smem + SMEM_A + sw((unsigned)row, (unsigned)kg * 16)) =
                make_uint4(hi[0], hi[1], hi[2], hi[3]);
            #pragma unroll
            for (int j = 0; j < 4; ++j) {
                float cn = fmaf(c[j], C[j], -s[j] * S[j]);
                float sn = fmaf(s[j], C[j],  c[j] * S[j]);
                c[j] = cn; s[j] = sn;
            }
        }
    }

    // ---- Per-thread ldmatrix address components (warp tile 32 rows x 64 cols) ----
    const unsigned m0 = (unsigned)(wid >> 1) * 32u;   // warp M base (0,32,64,96)
    const unsigned nb = (unsigned)(wid & 1) * 64u;    // warp N base (0,64)
    const unsigned aRow  = m0 + (unsigned)(lane & 15);
    const unsigned aXr   = (aRow & 7u) << 4;
    const unsigned aC0   = (unsigned)(lane & 16);
    const uint32_t aBase0 = sb + SMEM_A + aRow * 256u;
    const uint32_t aBase1 = aBase0 + 16u * 256u;
    const unsigned bRl = (unsigned)((lane & 7) + ((lane & 16) ? 8 : 0));
    const unsigned bXr = (bRl & 7u) << 4;
    const unsigned bC0 = (unsigned)((lane & 8) ? 16 : 0);

    __syncthreads();   // A tile ready

    for (int it = 0; it < NT; ++it) {
        const int nt = (it + phase) & 7;

        CP_ASYNC_WAIT0();
        __syncthreads();   // B tile ready; all warps done with the other buffer

        if (it + 1 < NT) {
            const unsigned char* gBn = g_B + (size_t)(((it + 1 + phase) & 7)) * 32768;
            uint32_t bo = sb + SMEM_B + (unsigned)((it + 1) & 1) * 32768u;
            #pragma unroll
            for (int i2 = 0; i2 < 8; ++i2)
                CP_ASYNC16(bo + i2 * 4096 + tid * 16, gBn + i2 * 4096 + tid * 16);
            CP_ASYNC_COMMIT();
        }

        const uint32_t bBase = sb + SMEM_B + (unsigned)(it & 1) * 32768u;

        // acc[0..7]: m-frag 0 (rows m0+q, m0+8+q), acc[8..15]: m-frag 1 (rows +16)
        // acc[i] / acc[8+i] covers cols [8i, 8i+8) of the warp's 64-col region.
        float acc[16][4];
        #pragma unroll
        for (int i = 0; i < 16; ++i)
            #pragma unroll
            for (int j = 0; j < 4; ++j) acc[i][j] = 0.0f;

        #pragma unroll
        for (int ks = 0; ks < 8; ++ks) {
            const unsigned akb = ((unsigned)ks * 32u + aC0) ^ aXr;
            uint32_t a0[4], a1[4];
            LDSM_X4(a0, aBase0 + akb);
            LDSM_X4(a1, aBase1 + akb);

            const unsigned bkb = ((unsigned)ks * 32u + bC0) ^ bXr;
            #pragma unroll
            for (int np = 0; np < 4; ++np) {
                uint32_t bh[4];
                LDSM_X4(bh, bBase + (nb + np * 16u + bRl) * 256u + bkb);
                MMA16816(acc[np * 2],         a0, bh[0], bh[1]);
                MMA16816(acc[np * 2 + 1],     a0, bh[2], bh[3]);
                MMA16816(acc[8 + np * 2],     a1, bh[0], bh[1]);
                MMA16816(acc[8 + np * 2 + 1], a1, bh[2], bh[3]);
            }
        }

        // ---- Epilogue: butterfly transpose -> STG.128 (4 consecutive cols/lane) ----
        // Set (h, ss): rows m0 + 16h + 8ss + q (q = lane>>2), float2 slots t8 = col
        // block. After the 2 stages, lane lam (=lane&3) slot tau holds cols
        // 16*(tau>>1) + 4*lam + 2*(tau&1) .. +1 of the same row.
        {
            const int q   = lane >> 2;
            const int lam = lane & 3;
            const size_t rowbase = ((size_t)(mtile * 128) + m0) * DDIM
                                 + (size_t)nt * 128 + nb + 4 * lam;
            #pragma unroll
            for (int h = 0; h < 2; ++h) {
                #pragma unroll
                for (int ssv = 0; ssv < 2; ++ssv) {
                    float2 v[8];
                    #pragma unroll
                    for (int t = 0; t < 8; ++t) {
                        v[t].x = acc[8 * h + t][2 * ssv];
                        v[t].y = acc[8 * h + t][2 * ssv + 1];
                    }
                    xstage<1, 0>(v, lane);
                    xstage<0, 0>(v, lane);
                    float* rp = out + rowbase + (size_t)(16 * h + 8 * ssv + q) * DDIM;
                    #pragma unroll
                    for (int g = 0; g < 4; ++g)
                        STG_CS_V4F(rp + 16 * g,
                                   v[2 * g].x, v[2 * g].y,
                                   v[2 * g + 1].x, v[2 * g + 1].y);
                }
            }
        }
    }
}

// ---------------------------------------------------------------------------
extern "C" void kernel_launch(void* const* d_in, const int* in_sizes, int n_in,
                              void* d_out, int out_size)
{
    const int*   lengths = (const int*)d_in[0];
    const float* W       = (const float*)d_in[1];
    float*       out     = (float*)d_out;
    (void)in_sizes; (void)n_in;

    cudaFuncSetAttribute(gemm_kernel,
                         cudaFuncAttributeMaxDynamicSharedMemorySize, SMEM_TOTAL);

    long long pos_elems = (long long)MTOT * DDIM;
    float* mask_ptr = ((long long)out_size >= pos_elems + (long long)MTOT)
                          ? (out + pos_elems) : nullptr;

    wprep_kernel<<<64, 256>>>(W);
    gemm_kernel<<<MT, 256, SMEM_TOTAL>>>(lengths, out, mask_ptr);
}